// round 1
// baseline (speedup 1.0000x reference)
#include <cuda_runtime.h>

// ArcFaceLoss: N=8192 rows, C=32000 classes, S=30, M=0.5
// loss_row = log( sum_j exp(S*clamp(pred_j)) - exp(S*tc) + exp(S*tm) ) - S*tm
//   tc = clamp(pred[target]), tm = tc*cosM - sqrt(1-tc^2)*sinM  (if tc > -cosM)
//                             tc - sin(M)*M                      (else)
// output = mean over rows.

#define NROWS 8192
#define NCOLS 32000
#define NV4   (NCOLS / 4)   // 8000 float4 per row
#define TPB   256

__device__ float g_row_loss[NROWS];

// 2^t for t in [-44, 44], FMA/ALU pipes only (no MUFU).
// Magic-constant round-to-nearest + degree-4 poly + exponent bit injection.
__device__ __forceinline__ float fast_exp2(float t) {
    const float MAGIC = 12582912.0f;          // 1.5 * 2^23
    float z = t + MAGIC;                      // z holds round(t) in low mantissa bits
    int   i = __float_as_int(z);
    float f = t - (z - MAGIC);                // f in [-0.5, 0.5]
    float p = 0.0096181300f;
    p = fmaf(p, f, 0.0555041087f);
    p = fmaf(p, f, 0.2402265070f);
    p = fmaf(p, f, 0.6931471806f);
    p = fmaf(p, f, 1.0f);
    // (i<<23) == (n<<23) mod 2^32 because MAGIC's integer-bits low 9 bits are 0.
    return __int_as_float((i << 23) + __float_as_int(p));
}

__global__ void __launch_bounds__(TPB) arcface_rows_kernel(
    const float* __restrict__ pred, const int* __restrict__ tgt)
{
    __shared__ float s_partial[TPB / 32];
    __shared__ float s_tgtcos;
    __shared__ int   s_t;

    const int row = blockIdx.x;
    const int tid = threadIdx.x;

    // --- target index (dtype auto-detect: int64-LE has zero high words) ---
    if (tid == 0) {
        bool is64 = true;
        #pragma unroll
        for (int k = 0; k < 16; ++k) is64 = is64 && (tgt[2 * k + 1] == 0);
        s_t = is64 ? tgt[2 * row] : tgt[row];
    }
    __syncthreads();
    const int t  = s_t;
    const int q  = t >> 2;   // which float4 holds the target column
    const int qc = t & 3;

    const float4* rowp = reinterpret_cast<const float4*>(pred + (size_t)row * NCOLS);
    const float K = 43.2808512266689f;   // S * log2(e) = 30 * 1.4426950408889634

    float acc = 0.0f;
    for (int j = tid; j < NV4; j += TPB) {
        float4 v = rowp[j];
        // clamp in log2 domain: t = clamp(p*K, -K, K) == K*clamp(p,-1,1)
        float a0 = fminf(fmaxf(v.x * K, -K), K);
        float a1 = fminf(fmaxf(v.y * K, -K), K);
        float a2 = fminf(fmaxf(v.z * K, -K), K);
        float a3 = fminf(fmaxf(v.w * K, -K), K);
        acc += fast_exp2(a0);
        acc += fast_exp2(a1);
        acc += fast_exp2(a2);
        acc += fast_exp2(a3);
        if (j == q) {
            float c = (qc == 0) ? v.x : (qc == 1) ? v.y : (qc == 2) ? v.z : v.w;
            s_tgtcos = fminf(fmaxf(c, -1.0f), 1.0f);
        }
    }

    // deterministic reduction: warp shuffle then fixed-order shared combine
    #pragma unroll
    for (int o = 16; o > 0; o >>= 1)
        acc += __shfl_down_sync(0xffffffffu, acc, o);
    if ((tid & 31) == 0) s_partial[tid >> 5] = acc;
    __syncthreads();

    if (tid == 0) {
        float sum = 0.0f;
        #pragma unroll
        for (int w = 0; w < TPB / 32; ++w) sum += s_partial[w];

        const float cosM = 0.87758256189037276f;   // cos(0.5)
        const float sinM = 0.47942553860420301f;   // sin(0.5)
        const float MM   = 0.23971276930210150f;   // sin(0.5)*0.5
        const float THR  = -0.87758256189037276f;  // cos(pi-0.5)
        const float L2E  = 1.44269504088896340f;

        float tc = s_tgtcos;
        float tm = (tc > THR)
                 ? fmaf(tc, cosM, -sqrtf(fmaxf(1.0f - tc * tc, 0.0f)) * sinM)
                 : (tc - MM);

        float sum2 = sum - exp2f(30.0f * L2E * tc) + exp2f(30.0f * L2E * tm);
        g_row_loss[row] = logf(sum2) - 30.0f * tm;
    }
}

__global__ void __launch_bounds__(1024) arcface_reduce_kernel(float* __restrict__ out)
{
    __shared__ float sh[1024];
    const int tid = threadIdx.x;
    float s = 0.0f;
    #pragma unroll
    for (int k = 0; k < NROWS / 1024; ++k)
        s += g_row_loss[tid + k * 1024];
    sh[tid] = s;
    __syncthreads();
    #pragma unroll
    for (int off = 512; off > 0; off >>= 1) {
        if (tid < off) sh[tid] += sh[tid + off];
        __syncthreads();
    }
    if (tid == 0) out[0] = sh[0] * (1.0f / (float)NROWS);
}

extern "C" void kernel_launch(void* const* d_in, const int* in_sizes, int n_in,
                              void* d_out, int out_size)
{
    const float* pred = (const float*)d_in[0];
    const int*   tgt  = (const int*)d_in[1];
    float*       out  = (float*)d_out;

    arcface_rows_kernel<<<NROWS, TPB>>>(pred, tgt);
    arcface_reduce_kernel<<<1, 1024>>>(out);
}

// round 2
// speedup vs baseline: 1.0953x; 1.0953x over previous
#include <cuda_runtime.h>

// ArcFaceLoss: N=8192 rows, C=32000 classes, S=30, M=0.5
// loss_row = log( sum_j exp(S*clamp(pred_j)) - exp(S*tc) + exp(S*tm) ) - S*tm
// output = mean over rows. Single fused kernel (last-block reduction).

#define NROWS 8192
#define NCOLS 32000
#define NV4   (NCOLS / 4)   // 8000 float4 per row
#define TPB   256

__device__ float        g_row_loss[NROWS];
__device__ unsigned int g_done = 0;

typedef unsigned long long u64;

__device__ __forceinline__ u64 pk2(float lo, float hi) {
    u64 r; asm("mov.b64 %0, {%1, %2};" : "=l"(r) : "f"(lo), "f"(hi)); return r;
}
__device__ __forceinline__ void upk2(u64 v, float& lo, float& hi) {
    asm("mov.b64 {%0, %1}, %2;" : "=f"(lo), "=f"(hi) : "l"(v));
}
__device__ __forceinline__ void upk2i(u64 v, int& lo, int& hi) {
    asm("mov.b64 {%0, %1}, %2;" : "=r"(lo), "=r"(hi) : "l"(v));
}
__device__ __forceinline__ u64 add2(u64 a, u64 b) {
    u64 d; asm("add.rn.f32x2 %0, %1, %2;" : "=l"(d) : "l"(a), "l"(b)); return d;
}
__device__ __forceinline__ u64 fma2(u64 a, u64 b, u64 c) {
    u64 d; asm("fma.rn.f32x2 %0, %1, %2, %3;" : "=l"(d) : "l"(a), "l"(b), "l"(c)); return d;
}

__global__ void __launch_bounds__(TPB) arcface_fused_kernel(
    const float* __restrict__ pred, const int* __restrict__ tgt,
    float* __restrict__ out)
{
    __shared__ float s_partial[TPB / 32];
    __shared__ int   s_t;
    __shared__ int   s_last;

    const int row = blockIdx.x;
    const int tid = threadIdx.x;

    // target index (dtype auto-detect: int64-LE has zero high words)
    if (tid == 0) {
        bool is64 = true;
        #pragma unroll
        for (int k = 0; k < 16; ++k) is64 = is64 && (tgt[2 * k + 1] == 0);
        s_t = is64 ? tgt[2 * row] : tgt[row];
    }
    __syncthreads();
    const int t = s_t;

    const float4* rowp = reinterpret_cast<const float4*>(pred + (size_t)row * NCOLS);

    const float Kf    = 43.2808512266689f;      // S * log2(e)
    const float MAGIC = 12582912.0f;            // 1.5 * 2^23
    const u64 K2   = pk2(Kf, Kf);
    const u64 MG2  = pk2(MAGIC, MAGIC);
    const u64 M1_2 = pk2(-1.0f, -1.0f);
    const u64 C3_2 = pk2(0.0555041086f, 0.0555041086f);   // ln2^3/6
    const u64 C2_2 = pk2(0.2402265070f, 0.2402265070f);   // ln2^2/2
    const u64 C1_2 = pk2(0.6931471806f, 0.6931471806f);   // ln2
    const u64 ONE2 = pk2(1.0f, 1.0f);

    u64 accA = pk2(0.0f, 0.0f);
    u64 accB = pk2(0.0f, 0.0f);

    #pragma unroll 2
    for (int j = tid; j < NV4; j += TPB) {
        float4 v = __ldcs(rowp + j);
        float c0 = fminf(fmaxf(v.x, -1.0f), 1.0f);
        float c1 = fminf(fmaxf(v.y, -1.0f), 1.0f);
        float c2 = fminf(fmaxf(v.z, -1.0f), 1.0f);
        float c3 = fminf(fmaxf(v.w, -1.0f), 1.0f);
        u64 cA = pk2(c0, c1);
        u64 cB = pk2(c2, c3);

        // z = c*K + MAGIC  (low mantissa bits of z = round(c*K))
        u64 zA = fma2(cA, K2, MG2);
        u64 zB = fma2(cB, K2, MG2);
        // -n = -z + MAGIC  (n = rounded integer as float)
        u64 nnA = fma2(zA, M1_2, MG2);
        u64 nnB = fma2(zB, M1_2, MG2);
        // f = c*K - n, f in [-0.5, 0.5]
        u64 fA = fma2(cA, K2, nnA);
        u64 fB = fma2(cB, K2, nnB);
        // 2^f poly (degree 3, rel err < 7e-4)
        u64 pA = fma2(C3_2, fA, C2_2);
        u64 pB = fma2(C3_2, fB, C2_2);
        pA = fma2(pA, fA, C1_2);
        pB = fma2(pB, fB, C1_2);
        pA = fma2(pA, fA, ONE2);
        pB = fma2(pB, fB, ONE2);

        int i0, i1, i2, i3;
        upk2i(zA, i0, i1);
        upk2i(zB, i2, i3);
        float q0, q1, q2, q3;
        upk2(pA, q0, q1);
        upk2(pB, q2, q3);
        // exponent injection: (i<<23) + bits(p); MAGIC low 9 int-bits are 0 so
        // (i<<23) == (round(t)<<23) mod 2^32.
        float e0 = __int_as_float((i0 << 23) + __float_as_int(q0));
        float e1 = __int_as_float((i1 << 23) + __float_as_int(q1));
        float e2 = __int_as_float((i2 << 23) + __float_as_int(q2));
        float e3 = __int_as_float((i3 << 23) + __float_as_int(q3));

        accA = add2(accA, pk2(e0, e1));
        accB = add2(accB, pk2(e2, e3));
    }

    u64 accT = add2(accA, accB);
    float sl, sh;
    upk2(accT, sl, sh);
    float acc = sl + sh;

    // deterministic reduction: warp shuffle then fixed-order shared combine
    #pragma unroll
    for (int o = 16; o > 0; o >>= 1)
        acc += __shfl_down_sync(0xffffffffu, acc, o);
    if ((tid & 31) == 0) s_partial[tid >> 5] = acc;
    __syncthreads();

    if (tid == 0) {
        float sum = 0.0f;
        #pragma unroll
        for (int w = 0; w < TPB / 32; ++w) sum += s_partial[w];

        const float cosM = 0.87758256189037276f;   // cos(0.5)
        const float sinM = 0.47942553860420301f;   // sin(0.5)
        const float MM   = 0.23971276930210150f;   // sin(0.5)*0.5
        const float THR  = -0.87758256189037276f;  // cos(pi-0.5)
        const float L2E  = 1.44269504088896340f;

        float tc = fminf(fmaxf(pred[(size_t)row * NCOLS + t], -1.0f), 1.0f);
        float tm = (tc > THR)
                 ? fmaf(tc, cosM, -sqrtf(fmaxf(1.0f - tc * tc, 0.0f)) * sinM)
                 : (tc - MM);

        float sum2 = sum - exp2f(30.0f * L2E * tc) + exp2f(30.0f * L2E * tm);
        g_row_loss[row] = logf(sum2) - 30.0f * tm;
    }
    __syncthreads();

    // ── last-block deterministic final reduction ──
    if (tid == 0) {
        __threadfence();
        unsigned int old = atomicAdd(&g_done, 1u);
        s_last = (old == NROWS - 1) ? 1 : 0;
    }
    __syncthreads();
    if (s_last) {
        __threadfence();
        float s = 0.0f;
        #pragma unroll
        for (int k = 0; k < NROWS / TPB; ++k)
            s += g_row_loss[tid + k * TPB];
        #pragma unroll
        for (int o = 16; o > 0; o >>= 1)
            s += __shfl_down_sync(0xffffffffu, s, o);
        if ((tid & 31) == 0) s_partial[tid >> 5] = s;
        __syncthreads();
        if (tid == 0) {
            float tot = 0.0f;
            #pragma unroll
            for (int w = 0; w < TPB / 32; ++w) tot += s_partial[w];
            out[0] = tot * (1.0f / (float)NROWS);
            g_done = 0;   // reset for next graph replay
        }
    }
}

extern "C" void kernel_launch(void* const* d_in, const int* in_sizes, int n_in,
                              void* d_out, int out_size)
{
    const float* pred = (const float*)d_in[0];
    const int*   tgt  = (const int*)d_in[1];
    float*       out  = (float*)d_out;

    arcface_fused_kernel<<<NROWS, TPB>>>(pred, tgt, out);
}

// round 4
// speedup vs baseline: 1.1146x; 1.0177x over previous
#include <cuda_runtime.h>

// ArcFaceLoss: N=8192 rows, C=32000 classes, S=30, M=0.5
// Persistent single-wave kernel: 1184 CTAs (148 SMs x 8), each handles ~7 rows.
// loss_row = log( sum_j exp(S*clamp(pred_j)) - exp(S*tc) + exp(S*tm) ) - S*tm

#define NROWS 8192
#define NCOLS 32000
#define NV4   (NCOLS / 4)   // 8000 float4 per row
#define TPB   256
#define GRID  1184          // 148 * 8

__device__ float        g_cta_loss[GRID];
__device__ unsigned int g_done = 0;

typedef unsigned long long u64;

__device__ __forceinline__ u64 pk2(float lo, float hi) {
    u64 r; asm("mov.b64 %0, {%1, %2};" : "=l"(r) : "f"(lo), "f"(hi)); return r;
}
__device__ __forceinline__ void upk2(u64 v, float& lo, float& hi) {
    asm("mov.b64 {%0, %1}, %2;" : "=f"(lo), "=f"(hi) : "l"(v));
}
__device__ __forceinline__ void upk2i(u64 v, int& lo, int& hi) {
    asm("mov.b64 {%0, %1}, %2;" : "=r"(lo), "=r"(hi) : "l"(v));
}
__device__ __forceinline__ u64 add2(u64 a, u64 b) {
    u64 d; asm("add.rn.f32x2 %0, %1, %2;" : "=l"(d) : "l"(a), "l"(b)); return d;
}
__device__ __forceinline__ u64 fma2(u64 a, u64 b, u64 c) {
    u64 d; asm("fma.rn.f32x2 %0, %1, %2, %3;" : "=l"(d) : "l"(a), "l"(b), "l"(c)); return d;
}

__global__ void __launch_bounds__(TPB, 8) arcface_fused_kernel(
    const float* __restrict__ pred, const int* __restrict__ tgt,
    float* __restrict__ out)
{
    __shared__ float s_partial[2][TPB / 32];
    __shared__ int   s_last;

    const int bid = blockIdx.x;
    const int tid = threadIdx.x;

    // dtype auto-detect (uniform across all threads): int64-LE high words are 0
    bool is64 = true;
    #pragma unroll
    for (int k = 0; k < 16; ++k) is64 = is64 && (tgt[2 * k + 1] == 0);

    const float Kf    = 43.2808512266689f;      // S * log2(e)
    const float MAGIC = 12582912.0f;            // 1.5 * 2^23
    const u64 K2   = pk2(Kf, Kf);
    const u64 MG2  = pk2(MAGIC, MAGIC);
    const u64 M1_2 = pk2(-1.0f, -1.0f);
    const u64 C3_2 = pk2(0.0555041086f, 0.0555041086f);
    const u64 C2_2 = pk2(0.2402265070f, 0.2402265070f);
    const u64 C1_2 = pk2(0.6931471806f, 0.6931471806f);
    const u64 ONE2 = pk2(1.0f, 1.0f);

    float local_loss = 0.0f;   // meaningful on tid 0 only
    int par = 0;

    for (int row = bid; row < NROWS; row += GRID, par ^= 1) {
        const int t = is64 ? __ldg(&tgt[2 * row]) : __ldg(&tgt[row]);
        // prefetch target column value (completes under the main loop)
        const float tcraw = __ldg(&pred[(size_t)row * NCOLS + t]);

        const float4* rowp = reinterpret_cast<const float4*>(pred + (size_t)row * NCOLS);

        u64 accA = pk2(0.0f, 0.0f);
        u64 accB = pk2(0.0f, 0.0f);

        #pragma unroll 4
        for (int j = tid; j < NV4; j += TPB) {
            float4 v = __ldcs(rowp + j);
            float c0 = fminf(fmaxf(v.x, -1.0f), 1.0f);
            float c1 = fminf(fmaxf(v.y, -1.0f), 1.0f);
            float c2 = fminf(fmaxf(v.z, -1.0f), 1.0f);
            float c3 = fminf(fmaxf(v.w, -1.0f), 1.0f);
            u64 cA = pk2(c0, c1);
            u64 cB = pk2(c2, c3);

            // z = c*K + MAGIC  (low mantissa bits hold round(c*K))
            u64 zA = fma2(cA, K2, MG2);
            u64 zB = fma2(cB, K2, MG2);
            // -n = -z + MAGIC
            u64 nnA = fma2(zA, M1_2, MG2);
            u64 nnB = fma2(zB, M1_2, MG2);
            // f = c*K - n in [-0.5, 0.5]
            u64 fA = fma2(cA, K2, nnA);
            u64 fB = fma2(cB, K2, nnB);
            // 2^f degree-3 poly
            u64 pA = fma2(C3_2, fA, C2_2);
            u64 pB = fma2(C3_2, fB, C2_2);
            pA = fma2(pA, fA, C1_2);
            pB = fma2(pB, fB, C1_2);
            pA = fma2(pA, fA, ONE2);
            pB = fma2(pB, fB, ONE2);

            int i0, i1, i2, i3;
            upk2i(zA, i0, i1);
            upk2i(zB, i2, i3);
            float q0, q1, q2, q3;
            upk2(pA, q0, q1);
            upk2(pB, q2, q3);
            // exponent injection: (i<<23) + bits(p)
            float e0 = __int_as_float((i0 << 23) + __float_as_int(q0));
            float e1 = __int_as_float((i1 << 23) + __float_as_int(q1));
            float e2 = __int_as_float((i2 << 23) + __float_as_int(q2));
            float e3 = __int_as_float((i3 << 23) + __float_as_int(q3));

            accA = add2(accA, pk2(e0, e1));
            accB = add2(accB, pk2(e2, e3));
        }

        u64 accT = add2(accA, accB);
        float sl, sh;
        upk2(accT, sl, sh);
        float acc = sl + sh;

        #pragma unroll
        for (int o = 16; o > 0; o >>= 1)
            acc += __shfl_down_sync(0xffffffffu, acc, o);
        if ((tid & 31) == 0) s_partial[par][tid >> 5] = acc;
        __syncthreads();

        if (tid == 0) {
            float sum = 0.0f;
            #pragma unroll
            for (int w = 0; w < TPB / 32; ++w) sum += s_partial[par][w];

            const float cosM = 0.87758256189037276f;   // cos(0.5)
            const float sinM = 0.47942553860420301f;   // sin(0.5)
            const float MM   = 0.23971276930210150f;   // sin(0.5)*0.5
            const float THR  = -0.87758256189037276f;  // cos(pi-0.5)
            const float L2E  = 1.44269504088896340f;

            float tc = fminf(fmaxf(tcraw, -1.0f), 1.0f);
            float tm = (tc > THR)
                     ? fmaf(tc, cosM, -sqrtf(fmaxf(1.0f - tc * tc, 0.0f)) * sinM)
                     : (tc - MM);

            float sum2 = sum - exp2f(30.0f * L2E * tc) + exp2f(30.0f * L2E * tm);
            local_loss += logf(sum2) - 30.0f * tm;
        }
        // no second sync needed: s_partial is parity double-buffered
    }

    // ── deterministic final reduction by the last-arriving CTA ──
    if (tid == 0) {
        g_cta_loss[bid] = local_loss;
        __threadfence();
        unsigned int old = atomicAdd(&g_done, 1u);
        s_last = (old == GRID - 1) ? 1 : 0;
    }
    __syncthreads();
    if (s_last) {
        __threadfence();
        float s = 0.0f;
        for (int k = tid; k < GRID; k += TPB)
            s += g_cta_loss[k];
        #pragma unroll
        for (int o = 16; o > 0; o >>= 1)
            s += __shfl_down_sync(0xffffffffu, s, o);
        if ((tid & 31) == 0) s_partial[0][tid >> 5] = s;
        __syncthreads();
        if (tid == 0) {
            float tot = 0.0f;
            #pragma unroll
            for (int w = 0; w < TPB / 32; ++w) tot += s_partial[0][w];
            out[0] = tot * (1.0f / (float)NROWS);
            g_done = 0;   // reset for next graph replay
        }
    }
}

extern "C" void kernel_launch(void* const* d_in, const int* in_sizes, int n_in,
                              void* d_out, int out_size)
{
    const float* pred = (const float*)d_in[0];
    const int*   tgt  = (const int*)d_in[1];
    float*       out  = (float*)d_out;

    arcface_fused_kernel<<<GRID, TPB>>>(pred, tgt, out);
}